// round 1
// baseline (speedup 1.0000x reference)
#include <cuda_runtime.h>
#include <cuda_bf16.h>
#include <mma.h>

using namespace nvcuda;

#define NB 64
#define NN 1024
#define ND 128
#define THRESH 0.15f   // 0.5 - MARGIN(0.35)
#define TILE 64
#define LDS 144        // smem leading dim (bf16 elems), mult of 8, rows 32B-aligned

// Scratch (device globals; no allocation allowed)
__device__ __nv_bfloat16 g_P[(size_t)NB * NN * ND];   // compacted positives
__device__ __nv_bfloat16 g_Q[(size_t)NB * NN * ND];   // compacted negatives
__device__ int   g_npos[NB];
__device__ int   g_nneg[NB];
__device__ float g_bsum[NB];

// ---------------------------------------------------------------------------
// Kernel A: per-batch normalize + compact (pos->g_P, neg->g_Q) + zero padding
// grid = 64 CTAs (one per batch), 256 threads
// ---------------------------------------------------------------------------
__global__ void compact_normalize_kernel(const float* __restrict__ emb,
                                         const int*   __restrict__ labels)
{
    const int b = blockIdx.x;
    __shared__ int s_npos, s_nneg;
    __shared__ short s_dest[NN];
    __shared__ unsigned char s_ispos[NN];

    if (threadIdx.x == 0) { s_npos = 0; s_nneg = 0; g_bsum[b] = 0.0f; }
    __syncthreads();

    // classify rows, assign compacted slots
    for (int r = threadIdx.x; r < NN; r += blockDim.x) {
        int L = labels[b * NN + r];
        int ispos = (L == 1);
        int idx = ispos ? atomicAdd(&s_npos, 1) : atomicAdd(&s_nneg, 1);
        s_dest[r]  = (short)idx;
        s_ispos[r] = (unsigned char)ispos;
    }
    __syncthreads();

    const int npos = s_npos;
    const int nneg = s_nneg;
    if (threadIdx.x == 0) { g_npos[b] = npos; g_nneg[b] = nneg; }

    const int wid  = threadIdx.x >> 5;
    const int lane = threadIdx.x & 31;
    const int nw   = blockDim.x >> 5;

    // warp-per-row: normalize and scatter (coalesced along D)
    for (int r = wid; r < NN; r += nw) {
        const float* src = emb + ((size_t)b * NN + r) * ND;
        float v[4];
        float ss = 0.0f;
#pragma unroll
        for (int i = 0; i < 4; i++) { v[i] = src[lane + 32 * i]; ss += v[i] * v[i]; }
#pragma unroll
        for (int o = 16; o > 0; o >>= 1) ss += __shfl_xor_sync(0xFFFFFFFFu, ss, o);
        float inv = 1.0f / fmaxf(sqrtf(ss), 1e-12f);
        __nv_bfloat16* dst = (s_ispos[r] ? g_P : g_Q) + ((size_t)b * NN + (int)s_dest[r]) * ND;
#pragma unroll
        for (int i = 0; i < 4; i++) dst[lane + 32 * i] = __float2bfloat16(v[i] * inv);
    }
    __syncthreads();

    // zero-pad tails up to tile granularity so GEMM needs no masking
    const __nv_bfloat16 z = __float2bfloat16(0.0f);
    int pad_pos = min(NN, ((npos + TILE - 1) / TILE) * TILE);
    int pad_neg = min(NN, ((nneg + TILE - 1) / TILE) * TILE);
    for (int r = npos + wid; r < pad_pos; r += nw) {
        __nv_bfloat16* dst = g_P + ((size_t)b * NN + r) * ND;
#pragma unroll
        for (int i = 0; i < 4; i++) dst[lane + 32 * i] = z;
    }
    for (int r = nneg + wid; r < pad_neg; r += nw) {
        __nv_bfloat16* dst = g_Q + ((size_t)b * NN + r) * ND;
#pragma unroll
        for (int i = 0; i < 4; i++) dst[lane + 32 * i] = z;
    }
}

// ---------------------------------------------------------------------------
// Kernel B: 64x64-tile P@Q^T per batch via wmma bf16, fused relu(s-0.15) sum
// grid = (16, 16, 64), 256 threads (8 warps; warp tile = 16 rows x 32 cols)
// ---------------------------------------------------------------------------
__global__ void __launch_bounds__(256, 2)
hinge_gemm_kernel()
{
    const int b  = blockIdx.z;
    const int ti = blockIdx.y;   // pos tile
    const int tj = blockIdx.x;   // neg tile

    const int npos = g_npos[b];
    const int nneg = g_nneg[b];
    if (npos == 0 || nneg == 0) return;
    if (ti * TILE >= npos || tj * TILE >= nneg) return;

    __shared__ __align__(32) __nv_bfloat16 sA[TILE][LDS];
    __shared__ __align__(32) __nv_bfloat16 sB[TILE][LDS];
    __shared__ float s_tile;

    if (threadIdx.x == 0) s_tile = 0.0f;

    const __nv_bfloat16* P = g_P + ((size_t)b * NN + ti * TILE) * ND;
    const __nv_bfloat16* Q = g_Q + ((size_t)b * NN + tj * TILE) * ND;

    // cooperative load: 64 rows x 128 bf16 = 64 x 16 uint4 per tile
    for (int t = threadIdx.x; t < TILE * 16; t += 256) {
        int r = t >> 4, c = t & 15;
        *reinterpret_cast<uint4*>(&sA[r][c * 8]) =
            reinterpret_cast<const uint4*>(P + (size_t)r * ND)[c];
        *reinterpret_cast<uint4*>(&sB[r][c * 8]) =
            reinterpret_cast<const uint4*>(Q + (size_t)r * ND)[c];
    }
    __syncthreads();

    const int warp = threadIdx.x >> 5;
    const int wrow = warp >> 1;   // 0..3  -> rows wrow*16
    const int wcol = warp & 1;    // 0..1  -> cols wcol*32

    wmma::fragment<wmma::accumulator, 16, 16, 16, float> c0, c1;
    wmma::fill_fragment(c0, 0.0f);
    wmma::fill_fragment(c1, 0.0f);

    const __nv_bfloat16* aBase = &sA[wrow * 16][0];
    const __nv_bfloat16* bBase0 = &sB[wcol * 32][0];
    const __nv_bfloat16* bBase1 = &sB[wcol * 32 + 16][0];

#pragma unroll
    for (int k = 0; k < ND; k += 16) {
        wmma::fragment<wmma::matrix_a, 16, 16, 16, __nv_bfloat16, wmma::row_major> a;
        wmma::fragment<wmma::matrix_b, 16, 16, 16, __nv_bfloat16, wmma::col_major> b0, b1;
        wmma::load_matrix_sync(a,  aBase  + k, LDS);
        wmma::load_matrix_sync(b0, bBase0 + k, LDS);  // col_major: B[k][n] = sB[n][k]
        wmma::load_matrix_sync(b1, bBase1 + k, LDS);
        wmma::mma_sync(c0, a, b0, c0);
        wmma::mma_sync(c1, a, b1, c1);
    }

    // fused epilogue: relu(sim - 0.15), tile sum
    float s = 0.0f;
#pragma unroll
    for (int e = 0; e < c0.num_elements; e++) {
        s += fmaxf(c0.x[e] - THRESH, 0.0f);
        s += fmaxf(c1.x[e] - THRESH, 0.0f);
    }
#pragma unroll
    for (int o = 16; o > 0; o >>= 1) s += __shfl_xor_sync(0xFFFFFFFFu, s, o);

    __syncthreads();  // s_tile init visible
    if ((threadIdx.x & 31) == 0) atomicAdd(&s_tile, s);
    __syncthreads();
    if (threadIdx.x == 0) atomicAdd(&g_bsum[b], s_tile);
}

// ---------------------------------------------------------------------------
// Kernel C: finalize -> out[0] = sum_b(valid*bsum/nneg) / max(sum_b valid*npos, 1)
// ---------------------------------------------------------------------------
__global__ void finalize_kernel(float* __restrict__ out)
{
    __shared__ float sl[NB], sc[NB];
    int b = threadIdx.x;
    float ls = 0.0f, cnt = 0.0f;
    if (b < NB) {
        int np = g_npos[b], nn = g_nneg[b];
        if (np > 0 && nn > 0) {
            ls  = g_bsum[b] / (float)nn;
            cnt = (float)np;
        }
    }
    sl[b] = ls; sc[b] = cnt;
    __syncthreads();
    if (b == 0) {
        float L = 0.0f, C = 0.0f;
        for (int i = 0; i < NB; i++) { L += sl[i]; C += sc[i]; }
        out[0] = L / fmaxf(C, 1.0f);
    }
}

// ---------------------------------------------------------------------------
extern "C" void kernel_launch(void* const* d_in, const int* in_sizes, int n_in,
                              void* d_out, int out_size)
{
    const float* emb    = (const float*)d_in[0];
    const int*   labels = (const int*)d_in[1];
    float*       out    = (float*)d_out;

    compact_normalize_kernel<<<NB, 256>>>(emb, labels);

    dim3 grid(NN / TILE, NN / TILE, NB);   // (16, 16, 64); tiles early-exit via counts
    hinge_gemm_kernel<<<grid, 256>>>();

    finalize_kernel<<<1, NB>>>(out);
}

// round 2
// speedup vs baseline: 1.5243x; 1.5243x over previous
#include <cuda_runtime.h>
#include <cuda_bf16.h>
#include <mma.h>

using namespace nvcuda;

#define NB 64
#define NN 1024
#define ND 128
#define THRESH 0.15f   // 0.5 - MARGIN(0.35)
#define TILE 64
#define LDS 144        // smem leading dim (bf16 elems)

// Scratch (device globals; no allocation allowed)
__device__ __nv_bfloat16 g_P[(size_t)NB * NN * ND];   // compacted positives
__device__ __nv_bfloat16 g_Q[(size_t)NB * NN * ND];   // compacted negatives
__device__ unsigned short g_dest[NB * NN];            // rank | (ispos<<15)
__device__ int   g_npos[NB];
__device__ int   g_nneg[NB];
__device__ float g_bsum[NB];

// ---------------------------------------------------------------------------
// Kernel A0: per-batch compaction map via block scan + zero pad rows
// grid = 64, block = 1024
// ---------------------------------------------------------------------------
__global__ void __launch_bounds__(1024)
scan_kernel(const int* __restrict__ labels)
{
    const int b = blockIdx.x;
    const int t = threadIdx.x;
    const int lane = t & 31, w = t >> 5;

    __shared__ int wsum[32];

    int p = (labels[b * NN + t] == 1);

    // warp inclusive scan
    int incl = p;
#pragma unroll
    for (int o = 1; o < 32; o <<= 1) {
        int v = __shfl_up_sync(0xFFFFFFFFu, incl, o);
        if (lane >= o) incl += v;
    }
    if (lane == 31) wsum[w] = incl;
    __syncthreads();
    if (t < 32) {
        int v = wsum[t];
#pragma unroll
        for (int o = 1; o < 32; o <<= 1) {
            int u = __shfl_up_sync(0xFFFFFFFFu, v, o);
            if (lane >= o) v += u;
        }
        wsum[t] = v;
    }
    __syncthreads();

    int ex_pos = incl + (w > 0 ? wsum[w - 1] : 0) - p;  // exclusive pos rank
    int ex_neg = t - ex_pos;                            // exclusive neg rank
    g_dest[b * NN + t] = (unsigned short)((p ? ex_pos : ex_neg) | (p << 15));

    const int npos = wsum[31];
    const int nneg = NN - npos;
    if (t == 0) { g_npos[b] = npos; g_nneg[b] = nneg; g_bsum[b] = 0.0f; }

    // zero-pad tails to tile granularity (GEMM then needs no masking)
    const uint4 z4 = make_uint4(0u, 0u, 0u, 0u);
    int pad_pos = min(NN, ((npos + TILE - 1) / TILE) * TILE);
    int pad_neg = min(NN, ((nneg + TILE - 1) / TILE) * TILE);

    int nzp = (pad_pos - npos) * 16;   // uint4 per row = 128*2B/16B = 16
    for (int i = t; i < nzp; i += 1024) {
        int r = npos + (i >> 4), c = i & 15;
        reinterpret_cast<uint4*>(g_P + ((size_t)b * NN + r) * ND)[c] = z4;
    }
    int nzn = (pad_neg - nneg) * 16;
    for (int i = t; i < nzn; i += 1024) {
        int r = nneg + (i >> 4), c = i & 15;
        reinterpret_cast<uint4*>(g_Q + ((size_t)b * NN + r) * ND)[c] = z4;
    }
}

// ---------------------------------------------------------------------------
// Kernel A1: normalize + compacted scatter. One warp per row.
// grid = (NN/8, NB), block = 256 (8 warps)
// ---------------------------------------------------------------------------
__global__ void __launch_bounds__(256)
normalize_scatter_kernel(const float* __restrict__ emb)
{
    const int b = blockIdx.y;
    const int wid  = threadIdx.x >> 5;
    const int lane = threadIdx.x & 31;
    const int r = blockIdx.x * 8 + wid;

    const float* src = emb + ((size_t)b * NN + r) * ND;
    float v[4];
    float ss = 0.0f;
#pragma unroll
    for (int i = 0; i < 4; i++) { v[i] = src[lane + 32 * i]; ss += v[i] * v[i]; }
#pragma unroll
    for (int o = 16; o > 0; o >>= 1) ss += __shfl_xor_sync(0xFFFFFFFFu, ss, o);
    float inv = 1.0f / fmaxf(sqrtf(ss), 1e-12f);

    unsigned short d = g_dest[b * NN + r];
    int rank  = d & 0x7FFF;
    int ispos = d >> 15;
    __nv_bfloat16* dst = (ispos ? g_P : g_Q) + ((size_t)b * NN + rank) * ND;
#pragma unroll
    for (int i = 0; i < 4; i++) dst[lane + 32 * i] = __float2bfloat16(v[i] * inv);
}

// ---------------------------------------------------------------------------
// Kernel B: 64x64-tile P@Q^T per batch via wmma bf16, fused relu(s-0.15) sum
// grid = (16, 16, 64), 256 threads (8 warps; warp tile = 16 rows x 32 cols)
// ---------------------------------------------------------------------------
__global__ void __launch_bounds__(256, 2)
hinge_gemm_kernel()
{
    const int b  = blockIdx.z;
    const int ti = blockIdx.y;   // pos tile
    const int tj = blockIdx.x;   // neg tile

    const int npos = g_npos[b];
    const int nneg = g_nneg[b];
    if (npos == 0 || nneg == 0) return;
    if (ti * TILE >= npos || tj * TILE >= nneg) return;

    __shared__ __align__(32) __nv_bfloat16 sA[TILE][LDS];
    __shared__ __align__(32) __nv_bfloat16 sB[TILE][LDS];
    __shared__ float s_tile;

    if (threadIdx.x == 0) s_tile = 0.0f;

    const __nv_bfloat16* P = g_P + ((size_t)b * NN + ti * TILE) * ND;
    const __nv_bfloat16* Q = g_Q + ((size_t)b * NN + tj * TILE) * ND;

    for (int t = threadIdx.x; t < TILE * 16; t += 256) {
        int r = t >> 4, c = t & 15;
        *reinterpret_cast<uint4*>(&sA[r][c * 8]) =
            reinterpret_cast<const uint4*>(P + (size_t)r * ND)[c];
        *reinterpret_cast<uint4*>(&sB[r][c * 8]) =
            reinterpret_cast<const uint4*>(Q + (size_t)r * ND)[c];
    }
    __syncthreads();

    const int warp = threadIdx.x >> 5;
    const int wrow = warp >> 1;   // 0..3
    const int wcol = warp & 1;    // 0..1

    wmma::fragment<wmma::accumulator, 16, 16, 16, float> c0, c1;
    wmma::fill_fragment(c0, 0.0f);
    wmma::fill_fragment(c1, 0.0f);

    const __nv_bfloat16* aBase  = &sA[wrow * 16][0];
    const __nv_bfloat16* bBase0 = &sB[wcol * 32][0];
    const __nv_bfloat16* bBase1 = &sB[wcol * 32 + 16][0];

#pragma unroll
    for (int k = 0; k < ND; k += 16) {
        wmma::fragment<wmma::matrix_a, 16, 16, 16, __nv_bfloat16, wmma::row_major> a;
        wmma::fragment<wmma::matrix_b, 16, 16, 16, __nv_bfloat16, wmma::col_major> b0, b1;
        wmma::load_matrix_sync(a,  aBase  + k, LDS);
        wmma::load_matrix_sync(b0, bBase0 + k, LDS);
        wmma::load_matrix_sync(b1, bBase1 + k, LDS);
        wmma::mma_sync(c0, a, b0, c0);
        wmma::mma_sync(c1, a, b1, c1);
    }

    float s = 0.0f;
#pragma unroll
    for (int e = 0; e < c0.num_elements; e++) {
        s += fmaxf(c0.x[e] - THRESH, 0.0f);
        s += fmaxf(c1.x[e] - THRESH, 0.0f);
    }
#pragma unroll
    for (int o = 16; o > 0; o >>= 1) s += __shfl_xor_sync(0xFFFFFFFFu, s, o);

    __syncthreads();
    if ((threadIdx.x & 31) == 0) atomicAdd(&s_tile, s);
    __syncthreads();
    if (threadIdx.x == 0) atomicAdd(&g_bsum[b], s_tile);
}

// ---------------------------------------------------------------------------
// Kernel C: finalize
// ---------------------------------------------------------------------------
__global__ void finalize_kernel(float* __restrict__ out)
{
    __shared__ float sl[NB], sc[NB];
    int b = threadIdx.x;
    float ls = 0.0f, cnt = 0.0f;
    if (b < NB) {
        int np = g_npos[b], nn = g_nneg[b];
        if (np > 0 && nn > 0) {
            ls  = g_bsum[b] / (float)nn;
            cnt = (float)np;
        }
    }
    sl[b] = ls; sc[b] = cnt;
    __syncthreads();
    if (b == 0) {
        float L = 0.0f, C = 0.0f;
        for (int i = 0; i < NB; i++) { L += sl[i]; C += sc[i]; }
        out[0] = L / fmaxf(C, 1.0f);
    }
}

// ---------------------------------------------------------------------------
extern "C" void kernel_launch(void* const* d_in, const int* in_sizes, int n_in,
                              void* d_out, int out_size)
{
    const float* emb    = (const float*)d_in[0];
    const int*   labels = (const int*)d_in[1];
    float*       out    = (float*)d_out;

    scan_kernel<<<NB, 1024>>>(labels);

    dim3 gridA(NN / 8, NB);
    normalize_scatter_kernel<<<gridA, 256>>>(emb);

    dim3 gridB(NN / TILE, NN / TILE, NB);
    hinge_gemm_kernel<<<gridB, 256>>>();

    finalize_kernel<<<1, NB>>>(out);
}

// round 3
// speedup vs baseline: 2.0967x; 1.3755x over previous
#include <cuda_runtime.h>
#include <cuda_bf16.h>
#include <mma.h>

using namespace nvcuda;

#define NB 64
#define NN 1024
#define ND 128
#define THRESH 0.15f     // 0.5 - MARGIN(0.35)
#define TILE 128         // CTA tile (both dims)
#define LDS 136          // smem leading dim (bf16), mult of 8
#define GEMM_CTAS (8 * 8 * NB)

// Scratch (device globals; no allocation allowed)
__device__ __nv_bfloat16 g_P[(size_t)NB * NN * ND];   // compacted positives
__device__ __nv_bfloat16 g_Q[(size_t)NB * NN * ND];   // compacted negatives
__device__ unsigned short g_dest[NB * NN];            // rank | (ispos<<15)
__device__ int   g_npos[NB];
__device__ int   g_nneg[NB];
__device__ float g_bsum[NB];
__device__ unsigned int g_done;                        // GEMM completion counter

// ---------------------------------------------------------------------------
// Kernel A0: per-batch compaction map via block scan + zero pad rows
// grid = 64, block = 1024
// ---------------------------------------------------------------------------
__global__ void __launch_bounds__(1024)
scan_kernel(const int* __restrict__ labels)
{
    const int b = blockIdx.x;
    const int t = threadIdx.x;
    const int lane = t & 31, w = t >> 5;

    __shared__ int wsum[32];

    int p = (labels[b * NN + t] == 1);

    int incl = p;
#pragma unroll
    for (int o = 1; o < 32; o <<= 1) {
        int v = __shfl_up_sync(0xFFFFFFFFu, incl, o);
        if (lane >= o) incl += v;
    }
    if (lane == 31) wsum[w] = incl;
    __syncthreads();
    if (t < 32) {
        int v = wsum[t];
#pragma unroll
        for (int o = 1; o < 32; o <<= 1) {
            int u = __shfl_up_sync(0xFFFFFFFFu, v, o);
            if (lane >= o) v += u;
        }
        wsum[t] = v;
    }
    __syncthreads();

    int ex_pos = incl + (w > 0 ? wsum[w - 1] : 0) - p;
    int ex_neg = t - ex_pos;
    g_dest[b * NN + t] = (unsigned short)((p ? ex_pos : ex_neg) | (p << 15));

    const int npos = wsum[31];
    const int nneg = NN - npos;
    if (t == 0) {
        g_npos[b] = npos; g_nneg[b] = nneg; g_bsum[b] = 0.0f;
        if (b == 0) g_done = 0u;           // reset GEMM completion counter
    }

    // zero-pad tails to TILE granularity (GEMM needs no masking)
    const uint4 z4 = make_uint4(0u, 0u, 0u, 0u);
    int pad_pos = min(NN, ((npos + TILE - 1) / TILE) * TILE);
    int pad_neg = min(NN, ((nneg + TILE - 1) / TILE) * TILE);

    int nzp = (pad_pos - npos) * 16;       // 16 uint4 per row
    for (int i = t; i < nzp; i += 1024) {
        int r = npos + (i >> 4), c = i & 15;
        reinterpret_cast<uint4*>(g_P + ((size_t)b * NN + r) * ND)[c] = z4;
    }
    int nzn = (pad_neg - nneg) * 16;
    for (int i = t; i < nzn; i += 1024) {
        int r = nneg + (i >> 4), c = i & 15;
        reinterpret_cast<uint4*>(g_Q + ((size_t)b * NN + r) * ND)[c] = z4;
    }
}

// ---------------------------------------------------------------------------
// Kernel A1: normalize + compacted scatter. One warp per row.
// grid = (NN/8, NB), block = 256
// ---------------------------------------------------------------------------
__global__ void __launch_bounds__(256)
normalize_scatter_kernel(const float* __restrict__ emb)
{
    const int b = blockIdx.y;
    const int wid  = threadIdx.x >> 5;
    const int lane = threadIdx.x & 31;
    const int r = blockIdx.x * 8 + wid;

    const float* src = emb + ((size_t)b * NN + r) * ND;
    float v[4];
    float ss = 0.0f;
#pragma unroll
    for (int i = 0; i < 4; i++) { v[i] = src[lane + 32 * i]; ss += v[i] * v[i]; }
#pragma unroll
    for (int o = 16; o > 0; o >>= 1) ss += __shfl_xor_sync(0xFFFFFFFFu, ss, o);
    float inv = 1.0f / fmaxf(sqrtf(ss), 1e-12f);

    unsigned short d = g_dest[b * NN + r];
    int rank  = d & 0x7FFF;
    int ispos = d >> 15;
    __nv_bfloat16* dst = (ispos ? g_P : g_Q) + ((size_t)b * NN + rank) * ND;
#pragma unroll
    for (int i = 0; i < 4; i++) dst[lane + 32 * i] = __float2bfloat16(v[i] * inv);
}

// ---------------------------------------------------------------------------
// Kernel B: 128x128-tile P@Q^T via wmma bf16, fused relu(s-0.15) sum,
// last-CTA finalize. grid = (8, 8, 64), 256 threads.
// Warp tile = 32 rows x 64 cols (warps in 4x2 arrangement).
// ---------------------------------------------------------------------------
__global__ void __launch_bounds__(256)
hinge_gemm_kernel(float* __restrict__ out)
{
    extern __shared__ __align__(16) char smem[];
    __nv_bfloat16 (*sA)[LDS] = reinterpret_cast<__nv_bfloat16(*)[LDS]>(smem);
    __nv_bfloat16 (*sB)[LDS] = reinterpret_cast<__nv_bfloat16(*)[LDS]>(smem + TILE * LDS * 2);
    __shared__ float s_tile;
    __shared__ unsigned int s_rank;

    const int b  = blockIdx.z;
    const int ti = blockIdx.y;
    const int tj = blockIdx.x;

    const int npos = g_npos[b];
    const int nneg = g_nneg[b];
    const bool active = (npos > 0) && (nneg > 0) &&
                        (ti * TILE < npos) && (tj * TILE < nneg);

    if (active) {
        if (threadIdx.x == 0) s_tile = 0.0f;

        const __nv_bfloat16* P = g_P + ((size_t)b * NN + ti * TILE) * ND;
        const __nv_bfloat16* Q = g_Q + ((size_t)b * NN + tj * TILE) * ND;

        // cooperative load: 128 rows x 16 uint4 per tile
        for (int t = threadIdx.x; t < TILE * 16; t += 256) {
            int r = t >> 4, c = t & 15;
            *reinterpret_cast<uint4*>(&sA[r][c * 8]) =
                reinterpret_cast<const uint4*>(P + (size_t)r * ND)[c];
            *reinterpret_cast<uint4*>(&sB[r][c * 8]) =
                reinterpret_cast<const uint4*>(Q + (size_t)r * ND)[c];
        }
        __syncthreads();

        const int warp = threadIdx.x >> 5;
        const int wrow = warp >> 1;   // 0..3 -> rows wrow*32
        const int wcol = warp & 1;    // 0..1 -> cols wcol*64

        wmma::fragment<wmma::accumulator, 16, 16, 16, float> acc[2][4];
#pragma unroll
        for (int i = 0; i < 2; i++)
#pragma unroll
            for (int j = 0; j < 4; j++) wmma::fill_fragment(acc[i][j], 0.0f);

#pragma unroll
        for (int k = 0; k < ND; k += 16) {
            wmma::fragment<wmma::matrix_a, 16, 16, 16, __nv_bfloat16, wmma::row_major> a[2];
            wmma::fragment<wmma::matrix_b, 16, 16, 16, __nv_bfloat16, wmma::col_major> bb[4];
#pragma unroll
            for (int i = 0; i < 2; i++)
                wmma::load_matrix_sync(a[i], &sA[wrow * 32 + i * 16][k], LDS);
#pragma unroll
            for (int j = 0; j < 4; j++)
                wmma::load_matrix_sync(bb[j], &sB[wcol * 64 + j * 16][k], LDS);
#pragma unroll
            for (int i = 0; i < 2; i++)
#pragma unroll
                for (int j = 0; j < 4; j++)
                    wmma::mma_sync(acc[i][j], a[i], bb[j], acc[i][j]);
        }

        float s = 0.0f;
#pragma unroll
        for (int i = 0; i < 2; i++)
#pragma unroll
            for (int j = 0; j < 4; j++)
#pragma unroll
                for (int e = 0; e < acc[i][j].num_elements; e++)
                    s += fmaxf(acc[i][j].x[e] - THRESH, 0.0f);

#pragma unroll
        for (int o = 16; o > 0; o >>= 1) s += __shfl_xor_sync(0xFFFFFFFFu, s, o);

        if ((threadIdx.x & 31) == 0) atomicAdd(&s_tile, s);
        __syncthreads();
        if (threadIdx.x == 0) atomicAdd(&g_bsum[b], s_tile);
    }

    // completion ticket; last CTA computes the final scalar
    if (threadIdx.x == 0) {
        __threadfence();
        s_rank = atomicAdd(&g_done, 1u);
    }
    __syncthreads();
    if (s_rank == GEMM_CTAS - 1 && threadIdx.x == 0) {
        __threadfence();
        float L = 0.0f, C = 0.0f;
        for (int i = 0; i < NB; i++) {
            int np = g_npos[i], nn = g_nneg[i];
            if (np > 0 && nn > 0) {
                L += g_bsum[i] / (float)nn;
                C += (float)np;
            }
        }
        out[0] = L / fmaxf(C, 1.0f);
    }
}

// ---------------------------------------------------------------------------
extern "C" void kernel_launch(void* const* d_in, const int* in_sizes, int n_in,
                              void* d_out, int out_size)
{
    const float* emb    = (const float*)d_in[0];
    const int*   labels = (const int*)d_in[1];
    float*       out    = (float*)d_out;

    const int smem_bytes = 2 * TILE * LDS * 2;  // sA + sB, bf16
    cudaFuncSetAttribute(hinge_gemm_kernel,
                         cudaFuncAttributeMaxDynamicSharedMemorySize, smem_bytes);

    scan_kernel<<<NB, 1024>>>(labels);

    dim3 gridA(NN / 8, NB);
    normalize_scatter_kernel<<<gridA, 256>>>(emb);

    dim3 gridB(NN / TILE, NN / TILE, NB);   // (8, 8, 64)
    hinge_gemm_kernel<<<gridB, 256, smem_bytes>>>(out);
}